// round 15
// baseline (speedup 1.0000x reference)
#include <cuda_runtime.h>
#include <cuda_fp16.h>
#include <cstdint>
#include <cstddef>

// ---------------------------------------------------------------------------
// StyledMLP: 3 chained modulated 1x1 convs (B=16, C=256, N=16384, S=512)
// Legacy mma.sync fp16 single-term; fp32 accumulate.
// R11: smem-crossbar-bound model. CTA 128Mx256N, 8 warps of 64x64 (2Mx4N),
// 1 CTA/SM: 88KB crossbar/chunk vs 98KB for two 128x128 CTAs (same output).
// ---------------------------------------------------------------------------

#define CB   16
#define CC   256
#define NN   16384
#define SS   512

#define BM 128
#define BN 256
#define BK 32
#define NT 256          // threads per CTA

// scratch (allocation-free rule: __device__ globals)
__device__ __half g_Xin[(size_t)CB * CC * NN];   // converted input
__device__ __half g_X0[(size_t)CB * CC * NN];    // layer0 out
__device__ __half g_X1[(size_t)CB * CC * NN];    // layer1 out
__device__ __half g_W[3 * CB * CC * CC];         // modulated fp16 weights
__device__ float  g_style[3 * CB * CC];

// ---------------------------------------------------------------------------
// PTX helpers
// ---------------------------------------------------------------------------
__device__ __forceinline__ void cp16(void* sdst, const void* gsrc) {
    unsigned a = (unsigned)__cvta_generic_to_shared(sdst);
    asm volatile("cp.async.cg.shared.global [%0], [%1], 16;\n" :: "r"(a), "l"(gsrc));
}
__device__ __forceinline__ void cp_commit() {
    asm volatile("cp.async.commit_group;\n" ::: "memory");
}
__device__ __forceinline__ void ldsm4(uint32_t* r, const void* p) {
    unsigned a = (unsigned)__cvta_generic_to_shared(p);
    asm volatile("ldmatrix.sync.aligned.m8n8.x4.shared.b16 {%0,%1,%2,%3}, [%4];\n"
                 : "=r"(r[0]), "=r"(r[1]), "=r"(r[2]), "=r"(r[3]) : "r"(a));
}
__device__ __forceinline__ void ldsm4t(uint32_t* r, const void* p) {
    unsigned a = (unsigned)__cvta_generic_to_shared(p);
    asm volatile("ldmatrix.sync.aligned.m8n8.x4.trans.shared.b16 {%0,%1,%2,%3}, [%4];\n"
                 : "=r"(r[0]), "=r"(r[1]), "=r"(r[2]), "=r"(r[3]) : "r"(a));
}
__device__ __forceinline__ void mma16816(float* c, const uint32_t* a, uint32_t b0, uint32_t b1) {
    asm volatile("mma.sync.aligned.m16n8k16.row.col.f32.f16.f16.f32 "
                 "{%0,%1,%2,%3}, {%4,%5,%6,%7}, {%8,%9}, {%0,%1,%2,%3};\n"
                 : "+f"(c[0]), "+f"(c[1]), "+f"(c[2]), "+f"(c[3])
                 : "r"(a[0]), "r"(a[1]), "r"(a[2]), "r"(a[3]), "r"(b0), "r"(b1));
}
__device__ __forceinline__ float warp_sum(float v) {
    #pragma unroll
    for (int o = 16; o; o >>= 1) v += __shfl_xor_sync(0xffffffffu, v, o);
    return v;
}

// ---------------------------------------------------------------------------
// Input conversion: x fp32 -> g_Xin fp16 (vectorized, one shot)
// ---------------------------------------------------------------------------
__global__ void cvt_kernel(const float* __restrict__ x) {
    size_t i = ((size_t)blockIdx.x * 256 + threadIdx.x) * 4;
    float4 v = *(const float4*)(x + i);
    __half2 p0 = __floats2half2_rn(v.x, v.y);
    __half2 p1 = __floats2half2_rn(v.z, v.w);
    uint2 u;
    u.x = *(uint32_t*)&p0;
    u.y = *(uint32_t*)&p1;
    *(uint2*)(g_Xin + i) = u;
}

// ---------------------------------------------------------------------------
// Modulation
// ---------------------------------------------------------------------------
struct ModArgs {
    const float* w[3];
    const float* mw[3];
    const float* mb[3];
};

__global__ void style_kernel(const float* __restrict__ z, ModArgs args) {
    int layer = blockIdx.x, b = blockIdx.y;
    int tid = threadIdx.x, warp = tid >> 5, lane = tid & 31;
    __shared__ float zs[SS];
    for (int i = tid; i < SS; i += 256) zs[i] = z[(size_t)b * SS + i];
    __syncthreads();

    const float* mw = args.mw[layer];
    const float* mb = args.mb[layer];
    for (int c = warp; c < CC; c += 8) {
        const float* row = mw + (size_t)c * SS;
        float s = 0.f;
        #pragma unroll
        for (int j = 0; j < SS / 32; j++)
            s = fmaf(row[lane + 32 * j], zs[lane + 32 * j], s);
        s = warp_sum(s);
        if (lane == 0)
            g_style[((size_t)layer * CB + b) * CC + c] =
                s * 0.04419417382415922f + mb[c];
    }
}

// grid (3, CB, 8): each block handles 32 rows
__global__ void modw_kernel(ModArgs args) {
    int layer = blockIdx.x, b = blockIdx.y, rg = blockIdx.z;
    int tid = threadIdx.x, warp = tid >> 5, lane = tid & 31;
    __shared__ float st[CC];
    for (int i = tid; i < CC; i += 256)
        st[i] = g_style[((size_t)layer * CB + b) * CC + i];
    __syncthreads();

    const float* w = args.w[layer];
    __half* ow = g_W + ((size_t)(layer * CB + b)) * CC * CC;

    for (int r = rg * 32 + warp; r < rg * 32 + 32; r += 8) {
        const float* wr = w + (size_t)r * CC;
        float s2 = 0.f;
        #pragma unroll
        for (int j = 0; j < CC / 32; j++) {
            float v = wr[lane + 32 * j] * st[lane + 32 * j];
            s2 = fmaf(v, v, s2);
        }
        s2 = warp_sum(s2);
        float ss = s2 * (0.0625f * 0.0625f) + 1e-8f;
        float d = rsqrtf(ss);
        d = d * (1.5f - 0.5f * ss * d * d);          // Newton refine
        float scale = 0.0625f * d;
        #pragma unroll
        for (int j = 0; j < CC / 32; j++) {
            int i = lane + 32 * j;
            ow[(size_t)r * CC + i] = __float2half_rn(wr[i] * st[i] * scale);
        }
    }
}

// ---------------------------------------------------------------------------
// GEMM smem layout (per stage, bytes), 2 stages:
//   [0,10240)       W : 128 rows x 40 fp16 (32 used + pad)
//   [10240,27136)   X : 32 rows x 264 fp16 (256 used + pad)
// ---------------------------------------------------------------------------
#define WPITCH 40
#define XP 264
#define PS 27136
#define SMEM_BYTES (2 * PS)

__device__ __forceinline__ void load_stage(char* sm, int stage,
                                           const __half* gW,
                                           const __half* Xp,
                                           int k0, int n0, int tid) {
    char* base = sm + stage * PS;
    #pragma unroll
    for (int i = 0; i < 2; i++) {                 // W: 128x32 fp16
        int c = tid + i * NT;                     // 0..511
        int row = c >> 2, cc = c & 3;
        cp16(base + (row * WPITCH + cc * 8) * 2, gW + (size_t)row * CC + k0 + cc * 8);
    }
    #pragma unroll
    for (int i = 0; i < 4; i++) {                 // X: 32x256 fp16
        int c = tid + i * NT;                     // 0..1023
        int row = c >> 5, cc = c & 31;
        cp16(base + 10240 + (row * XP + cc * 8) * 2,
             Xp + (size_t)(k0 + row) * NN + n0 + cc * 8);
    }
}

// ---------------------------------------------------------------------------
// GEMM. CTA 128Mx256N, 8 warps (warp tile 64x64, grid 2Mx4N), K=256,
// 2-stage pipeline, one barrier per chunk, single fp16 MMA term. 1 CTA/SM.
// IN_SEL: 0 = g_Xin, 1 = g_X0, 2 = g_X1  (resolved in DEVICE code)
// OUT_SEL: 0 = fp32 harness out, 1 = g_X0, 2 = g_X1
// ---------------------------------------------------------------------------
template<int IN_SEL, int OUT_SEL>
__global__ void __launch_bounds__(NT, 1)
gemm_kernel(const float* __restrict__ bias, float* __restrict__ yout, int layer) {
    extern __shared__ __align__(128) char sm[];

    const __half* Xin = (IN_SEL == 0) ? g_Xin : (IN_SEL == 1 ? g_X0 : g_X1);

    int b  = blockIdx.z;
    int m0 = blockIdx.y * BM;
    int n0 = blockIdx.x * BN;
    int tid  = threadIdx.x;
    int lane = tid & 31;
    int warp = tid >> 5;
    int wm = warp & 1;      // 2 warps along M (64 rows each)
    int wn = warp >> 1;     // 4 warps along N (64 cols each)

    const __half* gW = g_W + ((size_t)(layer * CB + b)) * CC * CC + (size_t)m0 * CC;
    const __half* Xp = Xin + (size_t)b * CC * NN;

    float acc[4][8][4];
    #pragma unroll
    for (int i = 0; i < 4; i++)
        #pragma unroll
        for (int j = 0; j < 8; j++)
            #pragma unroll
            for (int k = 0; k < 4; k++) acc[i][j][k] = 0.f;

    load_stage(sm, 0, gW, Xp, 0, n0, tid);
    cp_commit();

    #pragma unroll 1
    for (int ch = 0; ch < 8; ch++) {
        int stage = ch & 1;
        asm volatile("cp.async.wait_group 0;\n" ::: "memory");
        __syncthreads();   // stage data visible; stage^1 readers (chunk ch-1) done

        if (ch < 7) {
            load_stage(sm, stage ^ 1, gW, Xp, (ch + 1) * BK, n0, tid);
            cp_commit();
        }

        char* base = sm + stage * PS;
        const __half* Ws = (const __half*)base;
        const __half* Xs = (const __half*)(base + 10240);

        #pragma unroll
        for (int kk = 0; kk < BK; kk += 16) {
            uint32_t ah[4][4];
            #pragma unroll
            for (int mt = 0; mt < 4; mt++) {
                int row = wm * 64 + mt * 16 + (lane & 15);
                int col = kk + ((lane >> 4) << 3);
                ldsm4(ah[mt], &Ws[row * WPITCH + col]);
            }
            uint32_t bh[4][4];
            #pragma unroll
            for (int c2 = 0; c2 < 4; c2++) {
                int k = kk + ((lane >> 3) & 1) * 8 + (lane & 7);
                int n = wn * 64 + c2 * 16 + (lane >> 4) * 8;
                ldsm4t(bh[c2], &Xs[k * XP + n]);
            }
            #pragma unroll
            for (int nt = 0; nt < 8; nt++) {
                int c2 = nt >> 1, sub = (nt & 1) * 2;
                #pragma unroll
                for (int mt = 0; mt < 4; mt++)
                    mma16816(acc[mt][nt], ah[mt], bh[c2][sub], bh[c2][sub + 1]);
            }
        }
    }

    // epilogue: bias + leaky(0.2) * sqrt(2)
    const float S2 = 1.4142135623730951f;
    float* Yf = yout + (size_t)b * CC * NN;
    __half* Yp = ((OUT_SEL == 1) ? g_X0 : g_X1) + (size_t)b * CC * NN;

    #pragma unroll
    for (int mt = 0; mt < 4; mt++) {
        int r0 = m0 + wm * 64 + mt * 16 + (lane >> 2);
        float bv0 = __ldg(&bias[r0]);
        float bv1 = __ldg(&bias[r0 + 8]);
        #pragma unroll
        for (int nt = 0; nt < 8; nt++) {
            int cidx = n0 + wn * 64 + nt * 8 + 2 * (lane & 3);
            float y0 = acc[mt][nt][0] + bv0;
            float y1 = acc[mt][nt][1] + bv0;
            float y2 = acc[mt][nt][2] + bv1;
            float y3 = acc[mt][nt][3] + bv1;
            y0 = (y0 >= 0.f ? y0 : 0.2f * y0) * S2;
            y1 = (y1 >= 0.f ? y1 : 0.2f * y1) * S2;
            y2 = (y2 >= 0.f ? y2 : 0.2f * y2) * S2;
            y3 = (y3 >= 0.f ? y3 : 0.2f * y3) * S2;
            if (OUT_SEL == 0) {
                *(float2*)(Yf + (size_t)r0 * NN + cidx)       = make_float2(y0, y1);
                *(float2*)(Yf + (size_t)(r0 + 8) * NN + cidx) = make_float2(y2, y3);
            } else {
                __half2 p0; p0.x = __float2half_rn(y0); p0.y = __float2half_rn(y1);
                __half2 p1; p1.x = __float2half_rn(y2); p1.y = __float2half_rn(y3);
                *(__half2*)(Yp + (size_t)r0 * NN + cidx)       = p0;
                *(__half2*)(Yp + (size_t)(r0 + 8) * NN + cidx) = p1;
            }
        }
    }
}

// ---------------------------------------------------------------------------
extern "C" void kernel_launch(void* const* d_in, const int* in_sizes, int n_in,
                              void* d_out, int out_size) {
    (void)in_sizes; (void)n_in; (void)out_size;
    const float* x = (const float*)d_in[0];
    const float* z = (const float*)d_in[1];
    ModArgs ma;
    const float* bb[3];
    for (int l = 0; l < 3; l++) {
        ma.w[l]  = (const float*)d_in[2 + 4 * l];
        ma.mw[l] = (const float*)d_in[3 + 4 * l];
        ma.mb[l] = (const float*)d_in[4 + 4 * l];
        bb[l]    = (const float*)d_in[5 + 4 * l];
    }
    float* out = (float*)d_out;

    cudaFuncSetAttribute(gemm_kernel<0, 1>, cudaFuncAttributeMaxDynamicSharedMemorySize, SMEM_BYTES);
    cudaFuncSetAttribute(gemm_kernel<1, 2>, cudaFuncAttributeMaxDynamicSharedMemorySize, SMEM_BYTES);
    cudaFuncSetAttribute(gemm_kernel<2, 0>, cudaFuncAttributeMaxDynamicSharedMemorySize, SMEM_BYTES);

    cvt_kernel<<<(unsigned)((size_t)CB * CC * NN / (256 * 4)), 256>>>(x);
    style_kernel<<<dim3(3, CB), 256>>>(z, ma);
    modw_kernel<<<dim3(3, CB, 8), 256>>>(ma);

    dim3 grid(NN / BN, CC / BM, CB);
    gemm_kernel<0, 1><<<grid, NT, SMEM_BYTES>>>(bb[0], out, 0);
    gemm_kernel<1, 2><<<grid, NT, SMEM_BYTES>>>(bb[1], out, 1);
    gemm_kernel<2, 0><<<grid, NT, SMEM_BYTES>>>(bb[2], out, 2);
}

// round 16
// speedup vs baseline: 1.2704x; 1.2704x over previous
#include <cuda_runtime.h>
#include <cuda_fp16.h>
#include <cstdint>
#include <cstddef>

// ---------------------------------------------------------------------------
// StyledMLP: 3 chained modulated 1x1 convs (B=16, C=256, N=16384, S=512)
// Legacy mma.sync fp16 single-term; fp32 accumulate.
// R12: (a) layer-0 reads harness fp32 directly (cvt_kernel removed);
//      (b) fp16 layers use BK=64 (4 chunks) to halve per-chunk overhead.
// Geometry: CTA 128x128, 4 warps of 64x64, 2 CTAs/SM (best measured, R9).
// ---------------------------------------------------------------------------

#define CB   16
#define CC   256
#define NN   16384
#define SS   512

#define BM 128
#define BN 128
#define NT 128          // threads per CTA

// scratch (allocation-free rule: __device__ globals)
__device__ __half g_X0[(size_t)CB * CC * NN];    // layer0 out
__device__ __half g_X1[(size_t)CB * CC * NN];    // layer1 out
__device__ __half g_W[3 * CB * CC * CC];         // modulated fp16 weights
__device__ float  g_style[3 * CB * CC];

// ---------------------------------------------------------------------------
// PTX helpers
// ---------------------------------------------------------------------------
__device__ __forceinline__ void cp16(void* sdst, const void* gsrc) {
    unsigned a = (unsigned)__cvta_generic_to_shared(sdst);
    asm volatile("cp.async.cg.shared.global [%0], [%1], 16;\n" :: "r"(a), "l"(gsrc));
}
__device__ __forceinline__ void cp_commit() {
    asm volatile("cp.async.commit_group;\n" ::: "memory");
}
__device__ __forceinline__ void ldsm4(uint32_t* r, const void* p) {
    unsigned a = (unsigned)__cvta_generic_to_shared(p);
    asm volatile("ldmatrix.sync.aligned.m8n8.x4.shared.b16 {%0,%1,%2,%3}, [%4];\n"
                 : "=r"(r[0]), "=r"(r[1]), "=r"(r[2]), "=r"(r[3]) : "r"(a));
}
__device__ __forceinline__ void ldsm4t(uint32_t* r, const void* p) {
    unsigned a = (unsigned)__cvta_generic_to_shared(p);
    asm volatile("ldmatrix.sync.aligned.m8n8.x4.trans.shared.b16 {%0,%1,%2,%3}, [%4];\n"
                 : "=r"(r[0]), "=r"(r[1]), "=r"(r[2]), "=r"(r[3]) : "r"(a));
}
// pack two fp32 -> fp16x2 (low 16 = first/smaller-k element)
__device__ __forceinline__ uint32_t packf16(float lo, float hi) {
    uint32_t r;
    asm("cvt.rn.f16x2.f32 %0, %1, %2;" : "=r"(r) : "f"(hi), "f"(lo));
    return r;
}
__device__ __forceinline__ void mma16816(float* c, const uint32_t* a, uint32_t b0, uint32_t b1) {
    asm volatile("mma.sync.aligned.m16n8k16.row.col.f32.f16.f16.f32 "
                 "{%0,%1,%2,%3}, {%4,%5,%6,%7}, {%8,%9}, {%0,%1,%2,%3};\n"
                 : "+f"(c[0]), "+f"(c[1]), "+f"(c[2]), "+f"(c[3])
                 : "r"(a[0]), "r"(a[1]), "r"(a[2]), "r"(a[3]), "r"(b0), "r"(b1));
}
__device__ __forceinline__ float warp_sum(float v) {
    #pragma unroll
    for (int o = 16; o; o >>= 1) v += __shfl_xor_sync(0xffffffffu, v, o);
    return v;
}

// ---------------------------------------------------------------------------
// Modulation
// ---------------------------------------------------------------------------
struct ModArgs {
    const float* w[3];
    const float* mw[3];
    const float* mb[3];
};

__global__ void style_kernel(const float* __restrict__ z, ModArgs args) {
    int layer = blockIdx.x, b = blockIdx.y;
    int tid = threadIdx.x, warp = tid >> 5, lane = tid & 31;
    __shared__ float zs[SS];
    for (int i = tid; i < SS; i += 256) zs[i] = z[(size_t)b * SS + i];
    __syncthreads();

    const float* mw = args.mw[layer];
    const float* mb = args.mb[layer];
    for (int c = warp; c < CC; c += 8) {
        const float* row = mw + (size_t)c * SS;
        float s = 0.f;
        #pragma unroll
        for (int j = 0; j < SS / 32; j++)
            s = fmaf(row[lane + 32 * j], zs[lane + 32 * j], s);
        s = warp_sum(s);
        if (lane == 0)
            g_style[((size_t)layer * CB + b) * CC + c] =
                s * 0.04419417382415922f + mb[c];
    }
}

// grid (3, CB, 8): each block handles 32 rows
__global__ void modw_kernel(ModArgs args) {
    int layer = blockIdx.x, b = blockIdx.y, rg = blockIdx.z;
    int tid = threadIdx.x, warp = tid >> 5, lane = tid & 31;
    __shared__ float st[CC];
    for (int i = tid; i < CC; i += 256)
        st[i] = g_style[((size_t)layer * CB + b) * CC + i];
    __syncthreads();

    const float* w = args.w[layer];
    __half* ow = g_W + ((size_t)(layer * CB + b)) * CC * CC;

    for (int r = rg * 32 + warp; r < rg * 32 + 32; r += 8) {
        const float* wr = w + (size_t)r * CC;
        float s2 = 0.f;
        #pragma unroll
        for (int j = 0; j < CC / 32; j++) {
            float v = wr[lane + 32 * j] * st[lane + 32 * j];
            s2 = fmaf(v, v, s2);
        }
        s2 = warp_sum(s2);
        float ss = s2 * (0.0625f * 0.0625f) + 1e-8f;
        float d = rsqrtf(ss);
        d = d * (1.5f - 0.5f * ss * d * d);          // Newton refine
        float scale = 0.0625f * d;
        #pragma unroll
        for (int j = 0; j < CC / 32; j++) {
            int i = lane + 32 * j;
            ow[(size_t)r * CC + i] = __float2half_rn(wr[i] * st[i] * scale);
        }
    }
}

// ---------------------------------------------------------------------------
// Epilogue helper: bias + leaky(0.2)*sqrt(2); fp32 or fp16 output.
// ---------------------------------------------------------------------------
template<int OUT_F32>
__device__ __forceinline__ void epilogue(float acc[4][8][4], const float* bias,
                                         float* Yf, __half* Yp,
                                         int m0, int n0, int wm, int wn, int lane) {
    const float S2 = 1.4142135623730951f;
    #pragma unroll
    for (int mt = 0; mt < 4; mt++) {
        int r0 = m0 + wm * 64 + mt * 16 + (lane >> 2);
        float bv0 = __ldg(&bias[r0]);
        float bv1 = __ldg(&bias[r0 + 8]);
        #pragma unroll
        for (int nt = 0; nt < 8; nt++) {
            int cidx = n0 + wn * 64 + nt * 8 + 2 * (lane & 3);
            float y0 = acc[mt][nt][0] + bv0;
            float y1 = acc[mt][nt][1] + bv0;
            float y2 = acc[mt][nt][2] + bv1;
            float y3 = acc[mt][nt][3] + bv1;
            y0 = (y0 >= 0.f ? y0 : 0.2f * y0) * S2;
            y1 = (y1 >= 0.f ? y1 : 0.2f * y1) * S2;
            y2 = (y2 >= 0.f ? y2 : 0.2f * y2) * S2;
            y3 = (y3 >= 0.f ? y3 : 0.2f * y3) * S2;
            if (OUT_F32) {
                *(float2*)(Yf + (size_t)r0 * NN + cidx)       = make_float2(y0, y1);
                *(float2*)(Yf + (size_t)(r0 + 8) * NN + cidx) = make_float2(y2, y3);
            } else {
                __half2 p0; p0.x = __float2half_rn(y0); p0.y = __float2half_rn(y1);
                __half2 p1; p1.x = __float2half_rn(y2); p1.y = __float2half_rn(y3);
                *(__half2*)(Yp + (size_t)r0 * NN + cidx)       = p0;
                *(__half2*)(Yp + (size_t)(r0 + 8) * NN + cidx) = p1;
            }
        }
    }
}

// ===========================================================================
// Layer 0: fp32 input path. BK=32, 8 chunks.
// smem/stage: W 128x40 fp16 = 10240 ; X 32x132 f32 = 16896 ; PS0 = 27136
// ===========================================================================
#define WP0 40
#define SPF 132
#define PS0 27136
#define SMEM0 (2 * PS0)

__device__ __forceinline__ void load_stage0(char* sm, int stage,
                                            const __half* gW, const float* Xf,
                                            int k0, int n0, int tid) {
    char* base = sm + stage * PS0;
    #pragma unroll
    for (int i = 0; i < 4; i++) {                 // W: 128x32 fp16
        int c = tid + i * NT;                     // 0..511
        int row = c >> 2, cc = c & 3;
        cp16(base + (row * WP0 + cc * 8) * 2, gW + (size_t)row * CC + k0 + cc * 8);
    }
    #pragma unroll
    for (int i = 0; i < 8; i++) {                 // X fp32: 32x128
        int c = tid + i * NT;                     // 0..1023
        int row = c >> 5, cc = c & 31;
        cp16(base + 10240 + row * (SPF * 4) + cc * 16,
             Xf + (size_t)(k0 + row) * NN + n0 + cc * 4);
    }
}

__global__ void __launch_bounds__(NT, 2)
gemm0_kernel(const float* __restrict__ xin, const float* __restrict__ bias,
             int layer) {
    extern __shared__ __align__(128) char sm[];

    int b  = blockIdx.z;
    int m0 = blockIdx.y * BM;
    int n0 = blockIdx.x * BN;
    int tid  = threadIdx.x;
    int lane = tid & 31;
    int warp = tid >> 5;
    int wm = warp & 1;
    int wn = warp >> 1;

    const __half* gW = g_W + ((size_t)(layer * CB + b)) * CC * CC + (size_t)m0 * CC;
    const float* Xf = xin + (size_t)b * CC * NN;

    float acc[4][8][4];
    #pragma unroll
    for (int i = 0; i < 4; i++)
        #pragma unroll
        for (int j = 0; j < 8; j++)
            #pragma unroll
            for (int k = 0; k < 4; k++) acc[i][j][k] = 0.f;

    load_stage0(sm, 0, gW, Xf, 0, n0, tid);
    cp_commit();

    #pragma unroll 1
    for (int ch = 0; ch < 8; ch++) {
        int stage = ch & 1;
        asm volatile("cp.async.wait_group 0;\n" ::: "memory");
        __syncthreads();

        if (ch < 7) {
            load_stage0(sm, stage ^ 1, gW, Xf, (ch + 1) * 32, n0, tid);
            cp_commit();
        }

        char* base = sm + stage * PS0;
        const __half* Ws = (const __half*)base;
        const float* Xst = (const float*)(base + 10240);

        #pragma unroll
        for (int kk = 0; kk < 32; kk += 16) {
            uint32_t ah[4][4];
            #pragma unroll
            for (int mt = 0; mt < 4; mt++) {
                int row = wm * 64 + mt * 16 + (lane & 15);
                int col = kk + ((lane >> 4) << 3);
                ldsm4(ah[mt], &Ws[row * WP0 + col]);
            }
            #pragma unroll
            for (int nt = 0; nt < 8; nt++) {
                int n  = wn * 64 + nt * 8 + (lane >> 2);
                int kb = kk + 2 * (lane & 3);
                const float* xp = Xst + kb * SPF + n;
                uint32_t b0 = packf16(xp[0], xp[SPF]);
                uint32_t b1 = packf16(xp[8 * SPF], xp[9 * SPF]);
                #pragma unroll
                for (int mt = 0; mt < 4; mt++)
                    mma16816(acc[mt][nt], ah[mt], b0, b1);
            }
        }
    }

    __half* Yp = g_X0 + (size_t)b * CC * NN;
    epilogue<0>(acc, bias, nullptr, Yp, m0, n0, wm, wn, lane);
}

// ===========================================================================
// Layers 1-2: fp16 input path. BK=64, 4 chunks.
// smem/stage: W 128x72 fp16 = 18432 ; X 64x136 fp16 = 17408 ; PS1 = 35840
// ===========================================================================
#define WP1 72
#define XP 136
#define PS1 35840
#define SMEM1 (2 * PS1)

__device__ __forceinline__ void load_stage1(char* sm, int stage,
                                            const __half* gW, const __half* Xp,
                                            int k0, int n0, int tid) {
    char* base = sm + stage * PS1;
    #pragma unroll
    for (int i = 0; i < 8; i++) {                 // W: 128x64 fp16
        int c = tid + i * NT;                     // 0..1023
        int row = c >> 3, cc = c & 7;
        cp16(base + (row * WP1 + cc * 8) * 2, gW + (size_t)row * CC + k0 + cc * 8);
    }
    #pragma unroll
    for (int i = 0; i < 8; i++) {                 // X: 64x128 fp16
        int c = tid + i * NT;                     // 0..1023
        int row = c >> 4, cc = c & 15;
        cp16(base + 18432 + (row * XP + cc * 8) * 2,
             Xp + (size_t)(k0 + row) * NN + n0 + cc * 8);
    }
}

// IN_SEL: 1 = g_X0, 2 = g_X1 ; OUT_SEL: 0 = fp32 harness out, 2 = g_X1
template<int IN_SEL, int OUT_SEL>
__global__ void __launch_bounds__(NT, 2)
gemm16_kernel(const float* __restrict__ bias, float* __restrict__ yout, int layer) {
    extern __shared__ __align__(128) char sm[];

    const __half* Xin = (IN_SEL == 1) ? g_X0 : g_X1;

    int b  = blockIdx.z;
    int m0 = blockIdx.y * BM;
    int n0 = blockIdx.x * BN;
    int tid  = threadIdx.x;
    int lane = tid & 31;
    int warp = tid >> 5;
    int wm = warp & 1;
    int wn = warp >> 1;

    const __half* gW = g_W + ((size_t)(layer * CB + b)) * CC * CC + (size_t)m0 * CC;
    const __half* Xp = Xin + (size_t)b * CC * NN;

    float acc[4][8][4];
    #pragma unroll
    for (int i = 0; i < 4; i++)
        #pragma unroll
        for (int j = 0; j < 8; j++)
            #pragma unroll
            for (int k = 0; k < 4; k++) acc[i][j][k] = 0.f;

    load_stage1(sm, 0, gW, Xp, 0, n0, tid);
    cp_commit();

    #pragma unroll 1
    for (int ch = 0; ch < 4; ch++) {
        int stage = ch & 1;
        asm volatile("cp.async.wait_group 0;\n" ::: "memory");
        __syncthreads();

        if (ch < 3) {
            load_stage1(sm, stage ^ 1, gW, Xp, (ch + 1) * 64, n0, tid);
            cp_commit();
        }

        char* base = sm + stage * PS1;
        const __half* Ws = (const __half*)base;
        const __half* Xs = (const __half*)(base + 18432);

        #pragma unroll
        for (int kk = 0; kk < 64; kk += 16) {
            uint32_t ah[4][4];
            #pragma unroll
            for (int mt = 0; mt < 4; mt++) {
                int row = wm * 64 + mt * 16 + (lane & 15);
                int col = kk + ((lane >> 4) << 3);
                ldsm4(ah[mt], &Ws[row * WP1 + col]);
            }
            uint32_t bh[4][4];
            #pragma unroll
            for (int c2 = 0; c2 < 4; c2++) {
                int k = kk + ((lane >> 3) & 1) * 8 + (lane & 7);
                int n = wn * 64 + c2 * 16 + (lane >> 4) * 8;
                ldsm4t(bh[c2], &Xs[k * XP + n]);
            }
            #pragma unroll
            for (int nt = 0; nt < 8; nt++) {
                int c2 = nt >> 1, sub = (nt & 1) * 2;
                #pragma unroll
                for (int mt = 0; mt < 4; mt++)
                    mma16816(acc[mt][nt], ah[mt], bh[c2][sub], bh[c2][sub + 1]);
            }
        }
    }

    float* Yf = yout + (size_t)b * CC * NN;
    __half* Yp = g_X1 + (size_t)b * CC * NN;
    epilogue<OUT_SEL == 0 ? 1 : 0>(acc, bias, Yf, Yp, m0, n0, wm, wn, lane);
}

// ---------------------------------------------------------------------------
extern "C" void kernel_launch(void* const* d_in, const int* in_sizes, int n_in,
                              void* d_out, int out_size) {
    (void)in_sizes; (void)n_in; (void)out_size;
    const float* x = (const float*)d_in[0];
    const float* z = (const float*)d_in[1];
    ModArgs ma;
    const float* bb[3];
    for (int l = 0; l < 3; l++) {
        ma.w[l]  = (const float*)d_in[2 + 4 * l];
        ma.mw[l] = (const float*)d_in[3 + 4 * l];
        ma.mb[l] = (const float*)d_in[4 + 4 * l];
        bb[l]    = (const float*)d_in[5 + 4 * l];
    }
    float* out = (float*)d_out;

    cudaFuncSetAttribute(gemm0_kernel, cudaFuncAttributeMaxDynamicSharedMemorySize, SMEM0);
    cudaFuncSetAttribute(gemm16_kernel<1, 2>, cudaFuncAttributeMaxDynamicSharedMemorySize, SMEM1);
    cudaFuncSetAttribute(gemm16_kernel<2, 0>, cudaFuncAttributeMaxDynamicSharedMemorySize, SMEM1);

    style_kernel<<<dim3(3, CB), 256>>>(z, ma);
    modw_kernel<<<dim3(3, CB, 8), 256>>>(ma);

    dim3 grid(NN / BN, CC / BM, CB);
    gemm0_kernel<<<grid, NT, SMEM0>>>(x, bb[0], 0);
    gemm16_kernel<1, 2><<<grid, NT, SMEM1>>>(bb[1], out, 1);
    gemm16_kernel<2, 0><<<grid, NT, SMEM1>>>(bb[2], out, 2);
}

// round 17
// speedup vs baseline: 1.2994x; 1.0229x over previous
#include <cuda_runtime.h>
#include <cuda_fp16.h>
#include <cstdint>
#include <cstddef>

// ---------------------------------------------------------------------------
// StyledMLP: 3 chained modulated 1x1 convs (B=16, C=256, N=16384, S=512)
// Legacy mma.sync fp16 single-term; fp32 accumulate.
// R13: BK=64 (4 chunks) for ALL layers, including the fp32-input layer 0.
// Geometry: CTA 128x128, 4 warps of 64x64, 2 CTAs/SM.
// ---------------------------------------------------------------------------

#define CB   16
#define CC   256
#define NN   16384
#define SS   512

#define BM 128
#define BN 128
#define NT 128          // threads per CTA

// scratch (allocation-free rule: __device__ globals)
__device__ __half g_X0[(size_t)CB * CC * NN];    // layer0 out
__device__ __half g_X1[(size_t)CB * CC * NN];    // layer1 out
__device__ __half g_W[3 * CB * CC * CC];         // modulated fp16 weights
__device__ float  g_style[3 * CB * CC];

// ---------------------------------------------------------------------------
// PTX helpers
// ---------------------------------------------------------------------------
__device__ __forceinline__ void cp16(void* sdst, const void* gsrc) {
    unsigned a = (unsigned)__cvta_generic_to_shared(sdst);
    asm volatile("cp.async.cg.shared.global [%0], [%1], 16;\n" :: "r"(a), "l"(gsrc));
}
__device__ __forceinline__ void cp_commit() {
    asm volatile("cp.async.commit_group;\n" ::: "memory");
}
__device__ __forceinline__ void ldsm4(uint32_t* r, const void* p) {
    unsigned a = (unsigned)__cvta_generic_to_shared(p);
    asm volatile("ldmatrix.sync.aligned.m8n8.x4.shared.b16 {%0,%1,%2,%3}, [%4];\n"
                 : "=r"(r[0]), "=r"(r[1]), "=r"(r[2]), "=r"(r[3]) : "r"(a));
}
__device__ __forceinline__ void ldsm4t(uint32_t* r, const void* p) {
    unsigned a = (unsigned)__cvta_generic_to_shared(p);
    asm volatile("ldmatrix.sync.aligned.m8n8.x4.trans.shared.b16 {%0,%1,%2,%3}, [%4];\n"
                 : "=r"(r[0]), "=r"(r[1]), "=r"(r[2]), "=r"(r[3]) : "r"(a));
}
// pack two fp32 -> fp16x2 (low 16 = first/smaller-k element)
__device__ __forceinline__ uint32_t packf16(float lo, float hi) {
    uint32_t r;
    asm("cvt.rn.f16x2.f32 %0, %1, %2;" : "=r"(r) : "f"(hi), "f"(lo));
    return r;
}
__device__ __forceinline__ void mma16816(float* c, const uint32_t* a, uint32_t b0, uint32_t b1) {
    asm volatile("mma.sync.aligned.m16n8k16.row.col.f32.f16.f16.f32 "
                 "{%0,%1,%2,%3}, {%4,%5,%6,%7}, {%8,%9}, {%0,%1,%2,%3};\n"
                 : "+f"(c[0]), "+f"(c[1]), "+f"(c[2]), "+f"(c[3])
                 : "r"(a[0]), "r"(a[1]), "r"(a[2]), "r"(a[3]), "r"(b0), "r"(b1));
}
__device__ __forceinline__ float warp_sum(float v) {
    #pragma unroll
    for (int o = 16; o; o >>= 1) v += __shfl_xor_sync(0xffffffffu, v, o);
    return v;
}

// ---------------------------------------------------------------------------
// Modulation
// ---------------------------------------------------------------------------
struct ModArgs {
    const float* w[3];
    const float* mw[3];
    const float* mb[3];
};

__global__ void style_kernel(const float* __restrict__ z, ModArgs args) {
    int layer = blockIdx.x, b = blockIdx.y;
    int tid = threadIdx.x, warp = tid >> 5, lane = tid & 31;
    __shared__ float zs[SS];
    for (int i = tid; i < SS; i += 256) zs[i] = z[(size_t)b * SS + i];
    __syncthreads();

    const float* mw = args.mw[layer];
    const float* mb = args.mb[layer];
    for (int c = warp; c < CC; c += 8) {
        const float* row = mw + (size_t)c * SS;
        float s = 0.f;
        #pragma unroll
        for (int j = 0; j < SS / 32; j++)
            s = fmaf(row[lane + 32 * j], zs[lane + 32 * j], s);
        s = warp_sum(s);
        if (lane == 0)
            g_style[((size_t)layer * CB + b) * CC + c] =
                s * 0.04419417382415922f + mb[c];
    }
}

// grid (3, CB, 8): each block handles 32 rows
__global__ void modw_kernel(ModArgs args) {
    int layer = blockIdx.x, b = blockIdx.y, rg = blockIdx.z;
    int tid = threadIdx.x, warp = tid >> 5, lane = tid & 31;
    __shared__ float st[CC];
    for (int i = tid; i < CC; i += 256)
        st[i] = g_style[((size_t)layer * CB + b) * CC + i];
    __syncthreads();

    const float* w = args.w[layer];
    __half* ow = g_W + ((size_t)(layer * CB + b)) * CC * CC;

    for (int r = rg * 32 + warp; r < rg * 32 + 32; r += 8) {
        const float* wr = w + (size_t)r * CC;
        float s2 = 0.f;
        #pragma unroll
        for (int j = 0; j < CC / 32; j++) {
            float v = wr[lane + 32 * j] * st[lane + 32 * j];
            s2 = fmaf(v, v, s2);
        }
        s2 = warp_sum(s2);
        float ss = s2 * (0.0625f * 0.0625f) + 1e-8f;
        float d = rsqrtf(ss);
        d = d * (1.5f - 0.5f * ss * d * d);          // Newton refine
        float scale = 0.0625f * d;
        #pragma unroll
        for (int j = 0; j < CC / 32; j++) {
            int i = lane + 32 * j;
            ow[(size_t)r * CC + i] = __float2half_rn(wr[i] * st[i] * scale);
        }
    }
}

// ---------------------------------------------------------------------------
// Epilogue helper: bias + leaky(0.2)*sqrt(2); fp32 or fp16 output.
// ---------------------------------------------------------------------------
template<int OUT_F32>
__device__ __forceinline__ void epilogue(float acc[4][8][4], const float* bias,
                                         float* Yf, __half* Yp,
                                         int m0, int n0, int wm, int wn, int lane) {
    const float S2 = 1.4142135623730951f;
    #pragma unroll
    for (int mt = 0; mt < 4; mt++) {
        int r0 = m0 + wm * 64 + mt * 16 + (lane >> 2);
        float bv0 = __ldg(&bias[r0]);
        float bv1 = __ldg(&bias[r0 + 8]);
        #pragma unroll
        for (int nt = 0; nt < 8; nt++) {
            int cidx = n0 + wn * 64 + nt * 8 + 2 * (lane & 3);
            float y0 = acc[mt][nt][0] + bv0;
            float y1 = acc[mt][nt][1] + bv0;
            float y2 = acc[mt][nt][2] + bv1;
            float y3 = acc[mt][nt][3] + bv1;
            y0 = (y0 >= 0.f ? y0 : 0.2f * y0) * S2;
            y1 = (y1 >= 0.f ? y1 : 0.2f * y1) * S2;
            y2 = (y2 >= 0.f ? y2 : 0.2f * y2) * S2;
            y3 = (y3 >= 0.f ? y3 : 0.2f * y3) * S2;
            if (OUT_F32) {
                *(float2*)(Yf + (size_t)r0 * NN + cidx)       = make_float2(y0, y1);
                *(float2*)(Yf + (size_t)(r0 + 8) * NN + cidx) = make_float2(y2, y3);
            } else {
                __half2 p0; p0.x = __float2half_rn(y0); p0.y = __float2half_rn(y1);
                __half2 p1; p1.x = __float2half_rn(y2); p1.y = __float2half_rn(y3);
                *(__half2*)(Yp + (size_t)r0 * NN + cidx)       = p0;
                *(__half2*)(Yp + (size_t)(r0 + 8) * NN + cidx) = p1;
            }
        }
    }
}

// ===========================================================================
// Layer 0: fp32 input path. BK=64, 4 chunks.
// smem/stage: W 128x72 fp16 = 18432 ; X 64x132 f32 = 33792 ; PS0 = 52224
// ===========================================================================
#define WP 72
#define SPF 132
#define PS0 52224
#define SMEM0 (2 * PS0)

__device__ __forceinline__ void load_stage0(char* sm, int stage,
                                            const __half* gW, const float* Xf,
                                            int k0, int n0, int tid) {
    char* base = sm + stage * PS0;
    #pragma unroll
    for (int i = 0; i < 8; i++) {                 // W: 128x64 fp16
        int c = tid + i * NT;                     // 0..1023
        int row = c >> 3, cc = c & 7;
        cp16(base + (row * WP + cc * 8) * 2, gW + (size_t)row * CC + k0 + cc * 8);
    }
    #pragma unroll
    for (int i = 0; i < 16; i++) {                // X fp32: 64x128
        int c = tid + i * NT;                     // 0..2047
        int row = c >> 5, cc = c & 31;
        cp16(base + 18432 + row * (SPF * 4) + cc * 16,
             Xf + (size_t)(k0 + row) * NN + n0 + cc * 4);
    }
}

__global__ void __launch_bounds__(NT, 2)
gemm0_kernel(const float* __restrict__ xin, const float* __restrict__ bias,
             int layer) {
    extern __shared__ __align__(128) char sm[];

    int b  = blockIdx.z;
    int m0 = blockIdx.y * BM;
    int n0 = blockIdx.x * BN;
    int tid  = threadIdx.x;
    int lane = tid & 31;
    int warp = tid >> 5;
    int wm = warp & 1;
    int wn = warp >> 1;

    const __half* gW = g_W + ((size_t)(layer * CB + b)) * CC * CC + (size_t)m0 * CC;
    const float* Xf = xin + (size_t)b * CC * NN;

    float acc[4][8][4];
    #pragma unroll
    for (int i = 0; i < 4; i++)
        #pragma unroll
        for (int j = 0; j < 8; j++)
            #pragma unroll
            for (int k = 0; k < 4; k++) acc[i][j][k] = 0.f;

    load_stage0(sm, 0, gW, Xf, 0, n0, tid);
    cp_commit();

    #pragma unroll 1
    for (int ch = 0; ch < 4; ch++) {
        int stage = ch & 1;
        asm volatile("cp.async.wait_group 0;\n" ::: "memory");
        __syncthreads();

        if (ch < 3) {
            load_stage0(sm, stage ^ 1, gW, Xf, (ch + 1) * 64, n0, tid);
            cp_commit();
        }

        char* base = sm + stage * PS0;
        const __half* Ws = (const __half*)base;
        const float* Xst = (const float*)(base + 18432);

        #pragma unroll
        for (int kk = 0; kk < 64; kk += 16) {
            uint32_t ah[4][4];
            #pragma unroll
            for (int mt = 0; mt < 4; mt++) {
                int row = wm * 64 + mt * 16 + (lane & 15);
                int col = kk + ((lane >> 4) << 3);
                ldsm4(ah[mt], &Ws[row * WP + col]);
            }
            #pragma unroll
            for (int nt = 0; nt < 8; nt++) {
                int n  = wn * 64 + nt * 8 + (lane >> 2);
                int kb = kk + 2 * (lane & 3);
                const float* xp = Xst + kb * SPF + n;
                uint32_t b0 = packf16(xp[0], xp[SPF]);
                uint32_t b1 = packf16(xp[8 * SPF], xp[9 * SPF]);
                #pragma unroll
                for (int mt = 0; mt < 4; mt++)
                    mma16816(acc[mt][nt], ah[mt], b0, b1);
            }
        }
    }

    __half* Yp = g_X0 + (size_t)b * CC * NN;
    epilogue<0>(acc, bias, nullptr, Yp, m0, n0, wm, wn, lane);
}

// ===========================================================================
// Layers 1-2: fp16 input path. BK=64, 4 chunks.
// smem/stage: W 128x72 fp16 = 18432 ; X 64x136 fp16 = 17408 ; PS1 = 35840
// ===========================================================================
#define XP 136
#define PS1 35840
#define SMEM1 (2 * PS1)

__device__ __forceinline__ void load_stage1(char* sm, int stage,
                                            const __half* gW, const __half* Xp,
                                            int k0, int n0, int tid) {
    char* base = sm + stage * PS1;
    #pragma unroll
    for (int i = 0; i < 8; i++) {                 // W: 128x64 fp16
        int c = tid + i * NT;                     // 0..1023
        int row = c >> 3, cc = c & 7;
        cp16(base + (row * WP + cc * 8) * 2, gW + (size_t)row * CC + k0 + cc * 8);
    }
    #pragma unroll
    for (int i = 0; i < 8; i++) {                 // X: 64x128 fp16
        int c = tid + i * NT;                     // 0..1023
        int row = c >> 4, cc = c & 15;
        cp16(base + 18432 + (row * XP + cc * 8) * 2,
             Xp + (size_t)(k0 + row) * NN + n0 + cc * 8);
    }
}

// IN_SEL: 1 = g_X0, 2 = g_X1 ; OUT_SEL: 0 = fp32 harness out, 2 = g_X1
template<int IN_SEL, int OUT_SEL>
__global__ void __launch_bounds__(NT, 2)
gemm16_kernel(const float* __restrict__ bias, float* __restrict__ yout, int layer) {
    extern __shared__ __align__(128) char sm[];

    const __half* Xin = (IN_SEL == 1) ? g_X0 : g_X1;

    int b  = blockIdx.z;
    int m0 = blockIdx.y * BM;
    int n0 = blockIdx.x * BN;
    int tid  = threadIdx.x;
    int lane = tid & 31;
    int warp = tid >> 5;
    int wm = warp & 1;
    int wn = warp >> 1;

    const __half* gW = g_W + ((size_t)(layer * CB + b)) * CC * CC + (size_t)m0 * CC;
    const __half* Xp = Xin + (size_t)b * CC * NN;

    float acc[4][8][4];
    #pragma unroll
    for (int i = 0; i < 4; i++)
        #pragma unroll
        for (int j = 0; j < 8; j++)
            #pragma unroll
            for (int k = 0; k < 4; k++) acc[i][j][k] = 0.f;

    load_stage1(sm, 0, gW, Xp, 0, n0, tid);
    cp_commit();

    #pragma unroll 1
    for (int ch = 0; ch < 4; ch++) {
        int stage = ch & 1;
        asm volatile("cp.async.wait_group 0;\n" ::: "memory");
        __syncthreads();

        if (ch < 3) {
            load_stage1(sm, stage ^ 1, gW, Xp, (ch + 1) * 64, n0, tid);
            cp_commit();
        }

        char* base = sm + stage * PS1;
        const __half* Ws = (const __half*)base;
        const __half* Xs = (const __half*)(base + 18432);

        #pragma unroll
        for (int kk = 0; kk < 64; kk += 16) {
            uint32_t ah[4][4];
            #pragma unroll
            for (int mt = 0; mt < 4; mt++) {
                int row = wm * 64 + mt * 16 + (lane & 15);
                int col = kk + ((lane >> 4) << 3);
                ldsm4(ah[mt], &Ws[row * WP + col]);
            }
            uint32_t bh[4][4];
            #pragma unroll
            for (int c2 = 0; c2 < 4; c2++) {
                int k = kk + ((lane >> 3) & 1) * 8 + (lane & 7);
                int n = wn * 64 + c2 * 16 + (lane >> 4) * 8;
                ldsm4t(bh[c2], &Xs[k * XP + n]);
            }
            #pragma unroll
            for (int nt = 0; nt < 8; nt++) {
                int c2 = nt >> 1, sub = (nt & 1) * 2;
                #pragma unroll
                for (int mt = 0; mt < 4; mt++)
                    mma16816(acc[mt][nt], ah[mt], bh[c2][sub], bh[c2][sub + 1]);
            }
        }
    }

    float* Yf = yout + (size_t)b * CC * NN;
    __half* Yp = g_X1 + (size_t)b * CC * NN;
    epilogue<OUT_SEL == 0 ? 1 : 0>(acc, bias, Yf, Yp, m0, n0, wm, wn, lane);
}

// ---------------------------------------------------------------------------
extern "C" void kernel_launch(void* const* d_in, const int* in_sizes, int n_in,
                              void* d_out, int out_size) {
    (void)in_sizes; (void)n_in; (void)out_size;
    const float* x = (const float*)d_in[0];
    const float* z = (const float*)d_in[1];
    ModArgs ma;
    const float* bb[3];
    for (int l = 0; l < 3; l++) {
        ma.w[l]  = (const float*)d_in[2 + 4 * l];
        ma.mw[l] = (const float*)d_in[3 + 4 * l];
        ma.mb[l] = (const float*)d_in[4 + 4 * l];
        bb[l]    = (const float*)d_in[5 + 4 * l];
    }
    float* out = (float*)d_out;

    cudaFuncSetAttribute(gemm0_kernel, cudaFuncAttributeMaxDynamicSharedMemorySize, SMEM0);
    cudaFuncSetAttribute(gemm16_kernel<1, 2>, cudaFuncAttributeMaxDynamicSharedMemorySize, SMEM1);
    cudaFuncSetAttribute(gemm16_kernel<2, 0>, cudaFuncAttributeMaxDynamicSharedMemorySize, SMEM1);

    style_kernel<<<dim3(3, CB), 256>>>(z, ma);
    modw_kernel<<<dim3(3, CB, 8), 256>>>(ma);

    dim3 grid(NN / BN, CC / BM, CB);
    gemm0_kernel<<<grid, NT, SMEM0>>>(x, bb[0], 0);
    gemm16_kernel<1, 2><<<grid, NT, SMEM1>>>(bb[1], out, 1);
    gemm16_kernel<2, 0><<<grid, NT, SMEM1>>>(bb[2], out, 2);
}